// round 7
// baseline (speedup 1.0000x reference)
#include <cuda_runtime.h>
#include <cuda_fp16.h>

#define BB    2
#define CC    64
#define NN    16384
#define KK    16
#define COUT  64
#define RR    128           // rows of combined matrix [W1-W2 ; W2]
#define TNB   128           // GEMM nodes per block

typedef unsigned long long ull;

// ---------------- scratch (device globals; no allocation allowed) ----------
__device__ float  g_mean[BB][CC];
__device__ ull    g_Msd[CC * RR];              // M duplicated as f32x2 pairs, 64 KB
__device__ __half g_Yh[(size_t)BB * NN * RR];  // 8 MB transformed features (fp16)

// ---------------- f32x2 helpers (sm_103a packed fp32 FMA) -------------------
#define FMA_F32X2(d, a, b) \
    asm("fma.rn.f32x2 %0, %1, %2, %0;" : "+l"(d) : "l"(a), "l"(b))

__device__ __forceinline__ ull pack2(float lo, float hi) {
    ull r;
    asm("mov.b64 %0, {%1, %2};" : "=l"(r) : "f"(lo), "f"(hi));
    return r;
}

// ---------------- mean over nodes + Msd build --------------------------------
// Blocks 0..127: g_mean[b][c] row reductions. Blocks 128..135: build g_Msd.
__global__ __launch_bounds__(256) void mean_kernel(const float* __restrict__ x,
                                                   const float* __restrict__ W) {
    if (blockIdx.x >= BB * CC) {
        // build duplicated combined matrix: Msd[c][r] = (m, m)
        int base = (blockIdx.x - BB * CC) * 256 + threadIdx.x;
        #pragma unroll
        for (int it = 0; it < 4; it++) {
            int e = base + it * 2048;          // 0 .. 8191
            int c = e >> 7, r = e & 127;
            float v;
            if (r < 64) v = W[r * 192 + c] - W[r * 192 + 64 + c];   // W1 - W2
            else        v = W[(r - 64) * 192 + 64 + c];             // W2
            g_Msd[c * RR + r] = pack2(v, v);
        }
        return;
    }
    int row = blockIdx.x;                 // b*CC + c
    const float4* xr = (const float4*)(x + (size_t)row * NN);
    float s = 0.f;
    for (int i = threadIdx.x; i < NN / 4; i += 256) {
        float4 v = xr[i];
        s += v.x + v.y + v.z + v.w;
    }
    __shared__ float sm[256];
    sm[threadIdx.x] = s;
    __syncthreads();
    for (int st = 128; st > 0; st >>= 1) {
        if (threadIdx.x < st) sm[threadIdx.x] += sm[threadIdx.x + st];
        __syncthreads();
    }
    if (threadIdx.x == 0)
        ((float*)g_mean)[row] = sm[0] * (1.0f / NN);
}

// ---------------- GEMM: Yh[b][n][r] = sum_c M[r][c] * x[b][c][n] -------------
// grid (128 n-tiles, 4 r-quarters, 2 b). 48 KB smem -> 4 blocks/SM (32 warps).
// Per-thread tile: 4 n (2 f32x2 pairs) x 4 r. No packing in the hot loop.
__global__ __launch_bounds__(256, 4) void gemm_kernel(const float* __restrict__ x) {
    __shared__ __align__(16) ull   Msd_s[CC][32];   // 16 KB (this r-quarter, dup'd)
    __shared__ __align__(16) float Xs[CC][TNB];     // 32 KB
    int b   = blockIdx.z;
    int rq  = blockIdx.y;                 // r-quarter: rows rq*32 .. +31
    int n0  = blockIdx.x * TNB;
    int tid = threadIdx.x;

    for (int i = tid; i < CC * 16; i += 256) {      // 1024 x 16B
        int c = i >> 4, rp = (i & 15) << 1;
        *(ulonglong2*)&Msd_s[c][rp] =
            *(const ulonglong2*)(g_Msd + c * RR + rq * 32 + rp);
    }
    const float* xb = x + (size_t)b * CC * NN;
    for (int i = tid; i < CC * TNB / 4; i += 256) {
        int c = i >> 5, j = i & 31;
        ((float4*)&Xs[c][0])[j] = ((const float4*)(xb + (size_t)c * NN + n0))[j];
    }
    __syncthreads();

    int rg = tid & 7;     // r = rq*32 + rg*4 .. +3
    int ng = tid >> 3;    // n = n0 + ng*4 .. +3 (2 node-pairs)
    ull acc[2][4];
    #pragma unroll
    for (int p = 0; p < 2; p++)
        #pragma unroll
        for (int r = 0; r < 4; r++) acc[p][r] = 0ull;

    #pragma unroll 8
    for (int c = 0; c < CC; c++) {
        ulonglong2 m01 = *(const ulonglong2*)&Msd_s[c][rg * 4];
        ulonglong2 m23 = *(const ulonglong2*)&Msd_s[c][rg * 4 + 2];
        ulonglong2 xv  = *(const ulonglong2*)&Xs[c][ng * 4];
        FMA_F32X2(acc[0][0], xv.x, m01.x);
        FMA_F32X2(acc[0][1], xv.x, m01.y);
        FMA_F32X2(acc[0][2], xv.x, m23.x);
        FMA_F32X2(acc[0][3], xv.x, m23.y);
        FMA_F32X2(acc[1][0], xv.y, m01.x);
        FMA_F32X2(acc[1][1], xv.y, m01.y);
        FMA_F32X2(acc[1][2], xv.y, m23.x);
        FMA_F32X2(acc[1][3], xv.y, m23.y);
    }

    __half* Yb = g_Yh + (size_t)b * NN * RR;
    #pragma unroll
    for (int p = 0; p < 2; p++) {
        #pragma unroll
        for (int s = 0; s < 2; s++) {
            int n = n0 + ng * 4 + 2 * p + s;
            float v[4];
            #pragma unroll
            for (int r = 0; r < 4; r++) {
                uint2 u = *(uint2*)&acc[p][r];
                v[r] = __uint_as_float(s == 0 ? u.x : u.y);
            }
            __half2 h0 = __floats2half2_rn(v[0], v[1]);
            __half2 h1 = __floats2half2_rn(v[2], v[3]);
            uint2 pk;
            pk.x = *(unsigned*)&h0; pk.y = *(unsigned*)&h1;
            *(uint2*)(Yb + (size_t)n * RR + rq * 32 + rg * 4) = pk;
        }
    }
}

// ---------------- gather + max-relu epilogue --------------------------------
// Block 256 thr = 8 warps, 64 nodes/block, warp handles 8 nodes serially.
// Per node: 32 independent half2 row-loads (16 k x {i,j}) -> high MLP.
// cvec (bias + W3.mean) computed per block from smem-staged W3.
__global__ __launch_bounds__(256) void gather_kernel(const void* __restrict__ eidx,
                                                     const float* __restrict__ W,
                                                     const float* __restrict__ bias,
                                                     float* __restrict__ out) {
    int bn   = blockIdx.x;               // 0..511
    int b    = bn >> 8;                  // 256 blocks per batch
    int n0   = (bn & 255) * 64;
    int tid  = threadIdx.x;
    int lane = tid & 31;
    int w    = tid >> 5;

    __shared__ int   s_idx[64][2][KK];   // 8 KB
    __shared__ float s_o[64][65];        // 16.25 KB; stages W3 first, then output
    __shared__ float s_cv[64];
    __shared__ float s_mean[64];

    // edge dtype detect (redundant per thread; broadcast L2 loads)
    const ull* ep = (const ull*)eidx;
    int is64 = 1;
    #pragma unroll
    for (int i = 0; i < 8; i++)
        if (ep[i] >= (ull)NN) is64 = 0;

    // stage edge indices
    const long long* e64 = (const long long*)eidx;
    const int*       e32 = (const int*)eidx;
    for (int i = tid; i < 64 * KK; i += 256) {
        int ln = i >> 4, k = i & 15;
        size_t bj = ((size_t)(0 * BB + b) * NN + (n0 + ln)) * KK + k;
        size_t bi = ((size_t)(1 * BB + b) * NN + (n0 + ln)) * KK + k;
        int vi, vj;
        if (is64) { vj = (int)e64[bj]; vi = (int)e64[bi]; }
        else      { vj = e32[bj];      vi = e32[bi]; }
        s_idx[ln][0][k] = vi;            // center   (edge_index[1])
        s_idx[ln][1][k] = vj;            // neighbor (edge_index[0])
    }
    // stage W3 into s_o (as [o][c]) and mean
    for (int i = tid; i < COUT * CC; i += 256) {
        int o = i >> 6, c = i & 63;
        s_o[o][c] = W[o * 192 + 128 + c];
    }
    if (tid >= 192) s_mean[tid - 192] = g_mean[b][tid - 192];
    __syncthreads();

    if (tid < 64) {
        float s = bias[tid];
        #pragma unroll 8
        for (int c = 0; c < CC; c++)
            s = fmaf(s_o[tid][c], s_mean[c], s);
        s_cv[tid] = s;
    }
    __syncthreads();

    float2 cv = *(const float2*)&s_cv[2 * lane];   // channels 2*lane, 2*lane+1
    const __half* Yb = g_Yh + (size_t)b * NN * RR;

    for (int t = 0; t < 8; t++) {
        int ln = w * 8 + t;
        float m0 = 0.f, m1 = 0.f;        // relu floor folded into max
        #pragma unroll
        for (int k = 0; k < KK; k++) {
            int i = s_idx[ln][0][k];
            int j = s_idx[ln][1][k];
            __half2 hi = ((const __half2*)(Yb + (size_t)i * RR))[lane];
            __half2 hj = ((const __half2*)(Yb + (size_t)j * RR + 64))[lane];
            float2 fi = __half22float2(hi);
            float2 fj = __half22float2(hj);
            m0 = fmaxf(m0, fi.x + fj.x + cv.x);
            m1 = fmaxf(m1, fi.y + fj.y + cv.y);
        }
        s_o[ln][2 * lane]     = m0;
        s_o[ln][2 * lane + 1] = m1;
    }
    __syncthreads();

    float* ob = out + (size_t)b * COUT * NN;
    for (int i = tid; i < COUT * 64; i += 256) {
        int ch = i >> 6, j = i & 63;
        ob[ch * NN + n0 + j] = s_o[j][ch];
    }
}

// ---------------- launch ----------------------------------------------------
extern "C" void kernel_launch(void* const* d_in, const int* in_sizes, int n_in,
                              void* d_out, int out_size) {
    const float* x    = (const float*)d_in[0];
    const void*  eidx = d_in[1];
    const float* W    = (const float*)d_in[2];
    const float* bias = (const float*)d_in[3];
    float* out = (float*)d_out;

    mean_kernel<<<BB * CC + 8, 256>>>(x, W);
    gemm_kernel<<<dim3(NN / TNB, 4, BB), 256>>>(x);
    gather_kernel<<<BB * NN / 64, 256>>>(eidx, W, bias, out);
}